// round 2
// baseline (speedup 1.0000x reference)
#include <cuda_runtime.h>
#include <math.h>

// Problem constants (fixed shapes: B=2048, P=4, H=16, K=48, D=4, G=64)
#define PH 16      // H
#define PK 48      // K
#define PD 4       // D
#define PG 64      // G = H + K
#define LOG2PI 1.83787706640934548356f

__device__ __forceinline__ float warp_sum(float v) {
#pragma unroll
    for (int o = 16; o > 0; o >>= 1) v += __shfl_xor_sync(0xffffffffu, v, o);
    return v;
}

__global__ __launch_bounds__(256) void integ_kernel(
    const float* __restrict__ input_i,      // [BP, D]
    const float* __restrict__ Prev_coefs,   // [H, BP, H]
    const float* __restrict__ Prev_biases,  // [H, BP]
    const float* __restrict__ LP,           // [BP]
    const float* __restrict__ Log_factors,  // [BP]
    const float* __restrict__ obs_var,      // [K, BP, D]
    const float* __restrict__ hid_var,      // [K, BP, H]
    const float* __restrict__ next_var,     // [K, BP, H]
    const float* __restrict__ rec_biases,   // [K, BP]
    float* __restrict__ out, int BP)
{
    __shared__ float sMall[8][16 * 17];   // M then Cholesky L (per warp)
    __shared__ float sXall[8][17 * 17];   // X = M^{-1} A^T [Bm | c] transposed (per warp)

    const int warp = threadIdx.x >> 5;
    const int lane = threadIdx.x & 31;
    const int prob = blockIdx.x * 8 + warp;
    if (prob >= BP) return;

    float* sM = sMall[warp];
    float* sX = sXall[warp];

    // observation vector (D = 4)
    const float* xi = input_i + (size_t)prob * PD;
    float x0 = xi[0], x1 = xi[1], x2 = xi[2], x3 = xi[3];

    // Lane owns rows r0 = lane, r1 = lane + 32 of the 64-row system.
    float a0[16], a1[16], b0[16], b1[16], c0, c1;

    // ---- load row r0 ----
    if (lane < PH) {
        const float4* p = reinterpret_cast<const float4*>(
            Prev_coefs + ((size_t)lane * BP + prob) * PH);
#pragma unroll
        for (int q = 0; q < 4; q++) {
            float4 v = p[q];
            a0[4*q+0] = v.x; a0[4*q+1] = v.y; a0[4*q+2] = v.z; a0[4*q+3] = v.w;
        }
#pragma unroll
        for (int i = 0; i < 16; i++) b0[i] = 0.0f;
        c0 = Prev_biases[(size_t)lane * BP + prob];
    } else {
        int k = lane - PH;
        const float4* p = reinterpret_cast<const float4*>(
            hid_var + ((size_t)k * BP + prob) * PH);
        const float4* q4 = reinterpret_cast<const float4*>(
            next_var + ((size_t)k * BP + prob) * PH);
#pragma unroll
        for (int q = 0; q < 4; q++) {
            float4 v = p[q];
            a0[4*q+0] = v.x; a0[4*q+1] = v.y; a0[4*q+2] = v.z; a0[4*q+3] = v.w;
            float4 w = q4[q];
            b0[4*q+0] = w.x; b0[4*q+1] = w.y; b0[4*q+2] = w.z; b0[4*q+3] = w.w;
        }
        const float4 ov = *reinterpret_cast<const float4*>(
            obs_var + ((size_t)k * BP + prob) * PD);
        c0 = rec_biases[(size_t)k * BP + prob]
           + ov.x * x0 + ov.y * x1 + ov.z * x2 + ov.w * x3;
    }

    // ---- load row r1 (always a recurrent row, k = lane + 16) ----
    {
        int k = lane + (32 - PH);   // lane + 16
        const float4* p = reinterpret_cast<const float4*>(
            hid_var + ((size_t)k * BP + prob) * PH);
        const float4* q4 = reinterpret_cast<const float4*>(
            next_var + ((size_t)k * BP + prob) * PH);
#pragma unroll
        for (int q = 0; q < 4; q++) {
            float4 v = p[q];
            a1[4*q+0] = v.x; a1[4*q+1] = v.y; a1[4*q+2] = v.z; a1[4*q+3] = v.w;
            float4 w = q4[q];
            b1[4*q+0] = w.x; b1[4*q+1] = w.y; b1[4*q+2] = w.z; b1[4*q+3] = w.w;
        }
        const float4 ov = *reinterpret_cast<const float4*>(
            obs_var + ((size_t)k * BP + prob) * PD);
        c1 = rec_biases[(size_t)k * BP + prob]
           + ov.x * x0 + ov.y * x1 + ov.z * x2 + ov.w * x3;
    }

    // ---- M = A^T A (16x16 symmetric) ----
#pragma unroll
    for (int i = 0; i < 16; i++) {
#pragma unroll
        for (int j = i; j < 16; j++) {
            float s = warp_sum(a0[i] * a0[j] + a1[i] * a1[j]);
            if (lane == 0) { sM[i*17 + j] = s; sM[j*17 + i] = s; }
        }
    }
    __syncwarp();

    // ---- Cholesky M = L L^T (in place, lower triangle), lane i handles row i ----
    for (int j = 0; j < 16; j++) {
        if (lane == j) {
            float d = sM[j*17 + j];
            for (int t = 0; t < j; t++) { float l = sM[j*17 + t]; d -= l * l; }
            sM[j*17 + j] = sqrtf(d);
        }
        __syncwarp();
        float Ljj = sM[j*17 + j];
        if (lane > j && lane < 16) {
            float s = sM[lane*17 + j];
            for (int t = 0; t < j; t++) s -= sM[lane*17 + t] * sM[j*17 + t];
            sM[lane*17 + j] = s / Ljj;
        }
        __syncwarp();
    }

    // LC1 = -sum log L_jj  ( = -sum log |R1_jj| )
    float lc1 = warp_sum((lane < 16) ? -logf(sM[lane*17 + lane]) : 0.0f);

    // ---- N = A^T [Bm | c] ; lane k (<17) keeps column k in registers ----
    float y[16];
#pragma unroll
    for (int i = 0; i < 16; i++) {
#pragma unroll
        for (int k = 0; k < 16; k++) {
            float s = warp_sum(a0[i] * b0[k] + a1[i] * b1[k]);
            if (lane == k) y[i] = s;
        }
        float s = warp_sum(a0[i] * c0 + a1[i] * c1);
        if (lane == 16) y[i] = s;
    }

    // ---- solve M X = N : forward L y = n, backward L^T x = y ----
#pragma unroll
    for (int i = 0; i < 16; i++) {
        float s = y[i];
#pragma unroll
        for (int t = 0; t < i; t++) s -= sM[i*17 + t] * y[t];
        y[i] = s / sM[i*17 + i];
    }
#pragma unroll
    for (int i = 15; i >= 0; i--) {
        float s = y[i];
#pragma unroll
        for (int t = i + 1; t < 16; t++) s -= sM[t*17 + i] * y[t];
        y[i] = s / sM[i*17 + i];
    }
    if (lane < 17) {
#pragma unroll
        for (int i = 0; i < 16; i++) sX[lane*17 + i] = y[i];
    }
    __syncwarp();

    // ---- PB = Bm - A X,  Pc = c - A x_c ----
#pragma unroll
    for (int i = 0; i < 16; i++) {
        float ai0 = a0[i], ai1 = a1[i];
#pragma unroll
        for (int k = 0; k < 16; k++) {
            float xv = sX[k*17 + i];
            b0[k] -= ai0 * xv;
            b1[k] -= ai1 * xv;
        }
        float xc = sX[16*17 + i];
        c0 -= ai0 * xc;
        c1 -= ai1 * xc;
    }

    // ||Pc||^2 (before phase-2 QR, matching the reference formula)
    float pc2 = warp_sum(c0 * c0 + c1 * c1);

    // ---- Householder QR on PB (LAPACK slarfg convention), Pc carried ----
#pragma unroll
    for (int j = 0; j < 16; j++) {
        float alpha = __shfl_sync(0xffffffffu, b0[j], j);
        float part = (lane > j) ? b0[j] * b0[j] : 0.0f;
        float xn2 = warp_sum(part + b1[j] * b1[j]);

        float beta, tau, inv;
        if (xn2 == 0.0f) {
            beta = alpha; tau = 0.0f; inv = 0.0f;
        } else {
            beta = -copysignf(sqrtf(alpha * alpha + xn2), alpha);
            tau = (beta - alpha) / beta;
            inv = 1.0f / (alpha - beta);
        }

        float v0 = (lane == j) ? 1.0f : ((lane > j) ? b0[j] * inv : 0.0f);
        float v1 = b1[j] * inv;

        // finalize column j of R2
        if (lane == j)      b0[j] = beta;
        else if (lane > j)  b0[j] = 0.0f;
        b1[j] = 0.0f;

        // apply H = I - tau v v^T to remaining columns and Pc
#pragma unroll
        for (int k = j + 1; k < 16; k++) {
            float w = tau * warp_sum(v0 * b0[k] + v1 * b1[k]);
            b0[k] -= w * v0;
            b1[k] -= w * v1;
        }
        float wc = tau * warp_sum(v0 * c0 + v1 * c1);
        c0 -= wc * v0;
        c1 -= wc * v1;
    }

    // nb[j] = c0 on lane j (j < 16); resid = max(||Pc||^2 - ||nb||^2, 0)
    float nb2 = warp_sum((lane < 16) ? c0 * c0 : 0.0f);
    float resid = fmaxf(pc2 - nb2, 0.0f);
    float LC = lc1 - 0.5f * ((float)(PK - PH) * LOG2PI + resid);

    // ---- outputs ----
    // layout: Next_coefs [H,BP,H] | Next_biases [H,BP] | LP_new [BP]
    const size_t off1 = (size_t)PH * BP * PH;
    const size_t off2 = off1 + (size_t)PH * BP;

    if (lane < 16) {
        float4* po = reinterpret_cast<float4*>(out + ((size_t)lane * BP + prob) * PH);
        po[0] = make_float4(b0[0],  b0[1],  b0[2],  b0[3]);
        po[1] = make_float4(b0[4],  b0[5],  b0[6],  b0[7]);
        po[2] = make_float4(b0[8],  b0[9],  b0[10], b0[11]);
        po[3] = make_float4(b0[12], b0[13], b0[14], b0[15]);
        out[off1 + (size_t)lane * BP + prob] = c0;
    }
    if (lane == 0) {
        out[off2 + prob] = LP[prob] + LC + Log_factors[prob];
    }
}

extern "C" void kernel_launch(void* const* d_in, const int* in_sizes, int n_in,
                              void* d_out, int out_size) {
    const float* input_i     = (const float*)d_in[0];
    const float* Prev_coefs  = (const float*)d_in[1];
    const float* Prev_biases = (const float*)d_in[2];
    const float* LP          = (const float*)d_in[3];
    const float* Log_factors = (const float*)d_in[4];
    const float* obs_var     = (const float*)d_in[5];
    const float* hid_var     = (const float*)d_in[6];
    const float* next_var    = (const float*)d_in[7];
    const float* rec_biases  = (const float*)d_in[8];

    int BP = in_sizes[3];                 // B * P (size of LP)
    int blocks = (BP + 7) / 8;            // 8 warps per block, 1 problem per warp
    integ_kernel<<<blocks, 256>>>(input_i, Prev_coefs, Prev_biases, LP, Log_factors,
                                  obs_var, hid_var, next_var, rec_biases,
                                  (float*)d_out, BP);
}

// round 3
// speedup vs baseline: 1.8900x; 1.8900x over previous
#include <cuda_runtime.h>
#include <math.h>

// Fixed shapes: B=2048, P=4, H=16, K=48, D=4, G=64
#define PH 16
#define PK 48
#define PD 4
#define LOG2PI 1.83787706640934548356f

#define SA 66              // shared row stride (floats): odd*2 -> conflict-free
#define WPB 4              // warps (problems) per block

__device__ __forceinline__ float warp_sum(float v) {
#pragma unroll
    for (int o = 16; o > 0; o >>= 1) v += __shfl_xor_sync(0xffffffffu, v, o);
    return v;
}

// 64-length dot of two shared rows (8-byte aligned, stride-66 rows => no bank conflicts)
__device__ __forceinline__ float dot64(const float* p, const float* q) {
    const float2* P = reinterpret_cast<const float2*>(p);
    const float2* Q = reinterpret_cast<const float2*>(q);
    float s0 = 0.0f, s1 = 0.0f;
#pragma unroll
    for (int g = 0; g < 32; g++) {
        float2 u = P[g], v = Q[g];
        s0 = fmaf(u.x, v.x, s0);
        s1 = fmaf(u.y, v.y, s1);
    }
    return s0 + s1;
}

__global__ __launch_bounds__(128, 5) void integ_kernel(
    const float* __restrict__ input_i,      // [BP, D]
    const float* __restrict__ Prev_coefs,   // [H, BP, H]
    const float* __restrict__ Prev_biases,  // [H, BP]
    const float* __restrict__ LP,           // [BP]
    const float* __restrict__ Log_factors,  // [BP]
    const float* __restrict__ obs_var,      // [K, BP, D]
    const float* __restrict__ hid_var,      // [K, BP, H]
    const float* __restrict__ next_var,     // [K, BP, H]
    const float* __restrict__ rec_biases,   // [K, BP]
    float* __restrict__ out, int BP)
{
    __shared__ float sAt[WPB][16 * SA];   // A^T   (16 rows x 64 gaussians)
    __shared__ float sBt[WPB][17 * SA];   // [Bm|c]^T (17 rows x 64)
    __shared__ float sMm[WPB][16 * 17];   // Gram M -> Cholesky L (col 16 = 1/diag)
    __shared__ float sXx[WPB][17 * 17];   // N -> X = M^{-1} A^T [Bm|c], column-major

    const int warp = threadIdx.x >> 5;
    const int lane = threadIdx.x & 31;
    const int prob = blockIdx.x * WPB + warp;
    if (prob >= BP) return;

    float* At = sAt[warp];
    float* Bt = sBt[warp];
    float* sM = sMm[warp];
    float* sX = sXx[warp];

    const float4 xi = *reinterpret_cast<const float4*>(input_i + (size_t)prob * PD);

    // ---- load rows into shared (lane owns gaussians g0=lane, g1=lane+32) ----
    {
        float b0[16], b1[16], c0, c1;
        if (lane < PH) {
            const float4* p = reinterpret_cast<const float4*>(
                Prev_coefs + ((size_t)lane * BP + prob) * PH);
#pragma unroll
            for (int q = 0; q < 4; q++) {
                float4 v = p[q];
                At[(4*q+0)*SA + lane] = v.x; At[(4*q+1)*SA + lane] = v.y;
                At[(4*q+2)*SA + lane] = v.z; At[(4*q+3)*SA + lane] = v.w;
            }
#pragma unroll
            for (int i = 0; i < 16; i++) b0[i] = 0.0f;
            c0 = Prev_biases[(size_t)lane * BP + prob];
        } else {
            int k = lane - PH;
            const float4* p  = reinterpret_cast<const float4*>(
                hid_var + ((size_t)k * BP + prob) * PH);
            const float4* q4 = reinterpret_cast<const float4*>(
                next_var + ((size_t)k * BP + prob) * PH);
#pragma unroll
            for (int q = 0; q < 4; q++) {
                float4 v = p[q];
                At[(4*q+0)*SA + lane] = v.x; At[(4*q+1)*SA + lane] = v.y;
                At[(4*q+2)*SA + lane] = v.z; At[(4*q+3)*SA + lane] = v.w;
                float4 w = q4[q];
                b0[4*q+0] = w.x; b0[4*q+1] = w.y; b0[4*q+2] = w.z; b0[4*q+3] = w.w;
            }
            const float4 ov = *reinterpret_cast<const float4*>(
                obs_var + ((size_t)k * BP + prob) * PD);
            c0 = rec_biases[(size_t)k * BP + prob]
               + ov.x*xi.x + ov.y*xi.y + ov.z*xi.z + ov.w*xi.w;
        }
        {
            int k = lane + (32 - PH);
            const float4* p  = reinterpret_cast<const float4*>(
                hid_var + ((size_t)k * BP + prob) * PH);
            const float4* q4 = reinterpret_cast<const float4*>(
                next_var + ((size_t)k * BP + prob) * PH);
#pragma unroll
            for (int q = 0; q < 4; q++) {
                float4 v = p[q];
                At[(4*q+0)*SA + lane + 32] = v.x; At[(4*q+1)*SA + lane + 32] = v.y;
                At[(4*q+2)*SA + lane + 32] = v.z; At[(4*q+3)*SA + lane + 32] = v.w;
                float4 w = q4[q];
                b1[4*q+0] = w.x; b1[4*q+1] = w.y; b1[4*q+2] = w.z; b1[4*q+3] = w.w;
            }
            const float4 ov = *reinterpret_cast<const float4*>(
                obs_var + ((size_t)k * BP + prob) * PD);
            c1 = rec_biases[(size_t)k * BP + prob]
               + ov.x*xi.x + ov.y*xi.y + ov.z*xi.z + ov.w*xi.w;
        }
#pragma unroll
        for (int i = 0; i < 16; i++) {
            Bt[i*SA + lane]      = b0[i];
            Bt[i*SA + lane + 32] = b1[i];
        }
        Bt[16*SA + lane]      = c0;
        Bt[16*SA + lane + 32] = c1;
    }
    __syncwarp();

    // ---- M = A^T A : 136 upper-tri entries distributed over lanes ----
    for (int t = lane; t < 136; t += 32) {
        int i = 0, tt = t;
        while (tt >= 16 - i) { tt -= 16 - i; ++i; }
        int j = i + tt;
        float s = dot64(At + i*SA, At + j*SA);
        sM[i*17 + j] = s;
        if (i != j) sM[j*17 + i] = s;
    }

    // ---- column norms of [Bm|c] : lane k<17 owns column k ----
    float bn2 = 0.0f;
    if (lane < 17) bn2 = dot64(Bt + lane*SA, Bt + lane*SA);

    // ---- N = A^T [Bm|c] : 272 entries, t = k*16 + i ----
    for (int t = lane; t < 272; t += 32) {
        int i = t & 15;
        int k = t >> 4;
        sX[k*17 + i] = dot64(At + i*SA, Bt + k*SA);
    }
    __syncwarp();

    // ---- Cholesky M = L L^T (lane i handles row i) ----
    for (int j = 0; j < 16; j++) {
        if (lane == j) {
            float d = sM[j*17 + j];
            for (int t = 0; t < j; t++) { float l = sM[j*17 + t]; d = fmaf(-l, l, d); }
            sM[j*17 + j] = sqrtf(d);
        }
        __syncwarp();
        float Ljj = sM[j*17 + j];
        if (lane > j && lane < 16) {
            float s = sM[lane*17 + j];
            for (int t = 0; t < j; t++) s = fmaf(-sM[lane*17 + t], sM[j*17 + t], s);
            sM[lane*17 + j] = __fdividef(s, Ljj);
        }
        __syncwarp();
    }
    if (lane < 16) sM[lane*17 + 16] = 1.0f / sM[lane*17 + lane];  // reciprocal diag
    __syncwarp();

    float lc1 = warp_sum((lane < 16) ? -__logf(sM[lane*17 + lane]) : 0.0f);

    // ---- solve M X = N per column (lane k<17); s_own = ||P col_k||^2 via qn ----
    float s_own = 0.0f;
    if (lane < 17) {
        float y[16];
#pragma unroll
        for (int i = 0; i < 16; i++) y[i] = sX[lane*17 + i];
        // forward: y := L^{-1} N_k
#pragma unroll
        for (int i = 0; i < 16; i++) {
            float s = y[i];
#pragma unroll
            for (int t = 0; t < i; t++) s = fmaf(-sM[i*17 + t], y[t], s);
            y[i] = s * sM[i*17 + 16];
        }
        float qn = 0.0f;
#pragma unroll
        for (int i = 0; i < 16; i++) qn = fmaf(y[i], y[i], qn);
        s_own = bn2 - qn;       // ||(I - Q1 Q1^T) col_k||^2
        // backward: y := L^{-T} y
#pragma unroll
        for (int i = 15; i >= 0; i--) {
            float s = y[i];
#pragma unroll
            for (int t = i + 1; t < 16; t++) s = fmaf(-sM[t*17 + i], y[t], s);
            y[i] = s * sM[i*17 + 16];
        }
#pragma unroll
        for (int i = 0; i < 16; i++) sX[lane*17 + i] = y[i];
    }
    __syncwarp();

    // ---- projection: PB = Bm - A X, Pc = c - A x_c (back into registers) ----
    float b0[16], b1[16], c0, c1;
#pragma unroll
    for (int i = 0; i < 16; i++) {
        b0[i] = Bt[i*SA + lane];
        b1[i] = Bt[i*SA + lane + 32];
    }
    c0 = Bt[16*SA + lane];
    c1 = Bt[16*SA + lane + 32];
#pragma unroll
    for (int i = 0; i < 16; i++) {
        float ai0 = At[i*SA + lane];
        float ai1 = At[i*SA + lane + 32];
#pragma unroll
        for (int k = 0; k < 16; k++) {
            float xv = sX[k*17 + i];
            b0[k] = fmaf(-ai0, xv, b0[k]);
            b1[k] = fmaf(-ai1, xv, b1[k]);
        }
        float xc = sX[16*17 + i];
        c0 = fmaf(-ai0, xc, c0);
        c1 = fmaf(-ai1, xc, c1);
    }

    float pc2 = __shfl_sync(0xffffffffu, s_own, 16);   // ||Pc||^2

    // ---- Householder QR on PB (slarfg convention), norms downdated ----
#pragma unroll
    for (int j = 0; j < 16; j++) {
        float sj    = __shfl_sync(0xffffffffu, s_own, j);   // ||col j rows>=j||^2
        float alpha = __shfl_sync(0xffffffffu, b0[j], j);
        sj = fmaxf(sj, 1e-30f);
        float beta = -copysignf(sqrtf(sj), alpha);
        float tau  = __fdividef(beta - alpha, beta);
        float inv  = __fdividef(1.0f, alpha - beta);

        float v0 = (lane == j) ? 1.0f : ((lane > j) ? b0[j] * inv : 0.0f);
        float v1 = b1[j] * inv;

        if (lane == j)      b0[j] = beta;
        else if (lane > j)  b0[j] = 0.0f;
        b1[j] = 0.0f;

#pragma unroll
        for (int k = j + 1; k < 16; k++) {
            float w = tau * warp_sum(v0 * b0[k] + v1 * b1[k]);
            b0[k] = fmaf(-w, v0, b0[k]);
            b1[k] = fmaf(-w, v1, b1[k]);
            float r = __shfl_sync(0xffffffffu, b0[k], j);   // finalized R_{j,k}
            if (lane == k) s_own = fmaf(-r, r, s_own);
        }
        float wc = tau * warp_sum(v0 * c0 + v1 * c1);
        c0 = fmaf(-wc, v0, c0);
        c1 = fmaf(-wc, v1, c1);
    }

    float nb2 = warp_sum((lane < 16) ? c0 * c0 : 0.0f);
    float resid = fmaxf(pc2 - nb2, 0.0f);
    float LC = lc1 - 0.5f * ((float)(PK - PH) * LOG2PI + resid);

    // ---- outputs: Next_coefs [H,BP,H] | Next_biases [H,BP] | LP_new [BP] ----
    const size_t off1 = (size_t)PH * BP * PH;
    const size_t off2 = off1 + (size_t)PH * BP;

    if (lane < 16) {
        float4* po = reinterpret_cast<float4*>(out + ((size_t)lane * BP + prob) * PH);
        po[0] = make_float4(b0[0],  b0[1],  b0[2],  b0[3]);
        po[1] = make_float4(b0[4],  b0[5],  b0[6],  b0[7]);
        po[2] = make_float4(b0[8],  b0[9],  b0[10], b0[11]);
        po[3] = make_float4(b0[12], b0[13], b0[14], b0[15]);
        out[off1 + (size_t)lane * BP + prob] = c0;
    }
    if (lane == 0) {
        out[off2 + prob] = LP[prob] + LC + Log_factors[prob];
    }
}

extern "C" void kernel_launch(void* const* d_in, const int* in_sizes, int n_in,
                              void* d_out, int out_size) {
    const float* input_i     = (const float*)d_in[0];
    const float* Prev_coefs  = (const float*)d_in[1];
    const float* Prev_biases = (const float*)d_in[2];
    const float* LP          = (const float*)d_in[3];
    const float* Log_factors = (const float*)d_in[4];
    const float* obs_var     = (const float*)d_in[5];
    const float* hid_var     = (const float*)d_in[6];
    const float* next_var    = (const float*)d_in[7];
    const float* rec_biases  = (const float*)d_in[8];

    int BP = in_sizes[3];                     // B * P (size of LP)
    int blocks = (BP + WPB - 1) / WPB;        // 1 problem per warp, 4 warps/block
    integ_kernel<<<blocks, WPB * 32>>>(input_i, Prev_coefs, Prev_biases, LP, Log_factors,
                                       obs_var, hid_var, next_var, rec_biases,
                                       (float*)d_out, BP);
}